// round 8
// baseline (speedup 1.0000x reference)
#include <cuda_runtime.h>
#include <cuda_bf16.h>
#include <math.h>

#define N_NODES 50000
#define N_EDGES 1600000
#define N_GRAPHS 2048
#define DIM 133
#define HP 136           // padded row stride for g_h/g_t (16B aligned, zero pad)
#define EPS 1e-5f
#define NB 196           // ceil(50000/256)
#define WSTRIDE 136
#define KSTEPS 17        // 17*8 = 136 >= 133
#define NTILES 17

// ---------------- scratch (device globals; no allocation allowed) ----------------
__device__ float g_h[(size_t)N_NODES * HP];    // GEMM output (pre-aggregation), padded
__device__ float g_t[(size_t)N_NODES * HP];    // layer output (post BN), padded
__device__ int   g_cnt[N_NODES];               // in-degree histogram (no self loop)
__device__ int   g_off[N_NODES];               // CSR row offsets
__device__ int   g_cursor[N_NODES];            // scatter cursors
__device__ int2  g_edge[N_EDGES];              // CSR: {src, bitcast(dinv[src])}
__device__ float g_dinv[N_NODES];              // rsqrt(deg+1)
__device__ int   g_bsum[NB];                   // per-block histogram sums
__device__ int   g_goff[N_GRAPHS + 1];         // per-graph node ranges (batch sorted)

// ---------------- preprocessing ----------------
// zero histogram + per-graph ranges (independent elementwise work, one launch)
__global__ __launch_bounds__(256) void prep_kernel(const int* __restrict__ batch) {
    int i = blockIdx.x * blockDim.x + threadIdx.x;
    if (i >= N_NODES) return;
    g_cnt[i] = 0;
    int b = batch[i];
    int prev = (i == 0) ? -1 : batch[i - 1];
    for (int g = prev + 1; g <= b; g++) g_goff[g] = i;
    if (i == N_NODES - 1) {
        for (int g = b + 1; g <= N_GRAPHS; g++) g_goff[g] = N_NODES;
    }
}

__global__ void hist_kernel(const int* __restrict__ col) {
    for (int e = blockIdx.x * blockDim.x + threadIdx.x; e < N_EDGES;
         e += gridDim.x * blockDim.x) {
        atomicAdd(&g_cnt[col[e]], 1);
    }
}

// phase 1: per-block reduction of g_cnt
__global__ __launch_bounds__(256) void reduce_kernel() {
    int i = blockIdx.x * 256 + threadIdx.x;
    int v = (i < N_NODES) ? g_cnt[i] : 0;
    #pragma unroll
    for (int off = 16; off > 0; off >>= 1)
        v += __shfl_down_sync(0xFFFFFFFFu, v, off);
    __shared__ int ws[8];
    int lane = threadIdx.x & 31, w = threadIdx.x >> 5;
    if (lane == 0) ws[w] = v;
    __syncthreads();
    if (threadIdx.x == 0) {
        int s = 0;
        #pragma unroll
        for (int j = 0; j < 8; j++) s += ws[j];
        g_bsum[blockIdx.x] = s;
    }
}

// phase 2: block-local scan; each block reduces its own prefix of g_bsum inline
__global__ __launch_bounds__(256) void scan_apply_kernel() {
    int t = threadIdx.x;
    int lane = t & 31, w = t >> 5;

    // prefix = sum of g_bsum[0 .. blockIdx.x-1]  (NB=196 <= 256 threads)
    int pv = (t < blockIdx.x) ? g_bsum[t] : 0;
    #pragma unroll
    for (int off = 16; off > 0; off >>= 1)
        pv += __shfl_down_sync(0xFFFFFFFFu, pv, off);
    __shared__ int wred[8];
    __shared__ int pref;
    if (lane == 0) wred[w] = pv;
    __syncthreads();
    if (t == 0) {
        int s = 0;
        #pragma unroll
        for (int j = 0; j < 8; j++) s += wred[j];
        pref = s;
    }

    int i = blockIdx.x * 256 + t;
    int v = (i < N_NODES) ? g_cnt[i] : 0;
    int s = v;
    #pragma unroll
    for (int d = 1; d < 32; d <<= 1) {
        int tt = __shfl_up_sync(0xFFFFFFFFu, s, d);
        if (lane >= d) s += tt;
    }
    __shared__ int ws[8];
    __shared__ int wo[8];
    if (lane == 31) ws[w] = s;
    __syncthreads();
    if (t == 0) {
        int r = 0;
        #pragma unroll
        for (int j = 0; j < 8; j++) { wo[j] = r; r += ws[j]; }
    }
    __syncthreads();
    if (i < N_NODES) {
        int excl = pref + wo[w] + (s - v);
        g_off[i] = excl;
        g_cursor[i] = excl;
        g_dinv[i] = rsqrtf((float)(v + 1));   // +1 self loop
    }
}

// scatter: CSR by destination; pack (src, dinv[src]) per edge
__global__ void scatter_kernel(const int* __restrict__ row,
                               const int* __restrict__ col) {
    for (int e = blockIdx.x * blockDim.x + threadIdx.x; e < N_EDGES;
         e += gridDim.x * blockDim.x) {
        int c = col[e];
        int r = row[e];
        int p = atomicAdd(&g_cursor[c], 1);
        g_edge[p] = make_int2(r, __float_as_int(g_dinv[r]));
    }
}

// ---------- tf32 tensor-core GEMM: g_h[M,:] = A[M,133] @ W[133,133] ----------
__device__ __forceinline__ unsigned f2tf32(float f) {
    unsigned u;
    asm("cvt.rna.tf32.f32 %0, %1;" : "=r"(u) : "f"(f));
    return u;
}

__global__ __launch_bounds__(128) void gemm_tc_kernel(const float* __restrict__ A_ext,
                                                      const float* __restrict__ W,
                                                      int use_gt) {
    extern __shared__ unsigned Ws[];   // WSTRIDE * WSTRIDE tf32 words
    const float* __restrict__ A = use_gt ? (const float*)g_t : A_ext;
    const int lda = use_gt ? HP : DIM;
    int tid = threadIdx.x;

    for (int idx = tid; idx < WSTRIDE * WSTRIDE; idx += 128) {
        int k = idx / WSTRIDE, n = idx - k * WSTRIDE;
        float v = (k < DIM && n < DIM) ? W[k * DIM + n] : 0.f;
        Ws[idx] = f2tf32(v);
    }
    __syncthreads();

    int warp = tid >> 5, lane = tid & 31;
    int gid = lane >> 2;    // 0..7
    int tig = lane & 3;     // 0..3
    int m0 = blockIdx.x * 64 + warp * 16;

    float acc[NTILES][4];
    #pragma unroll
    for (int n = 0; n < NTILES; n++) {
        acc[n][0] = acc[n][1] = acc[n][2] = acc[n][3] = 0.f;
    }

    int r0 = m0 + gid;
    int r1 = m0 + gid + 8;
    bool v0 = r0 < N_NODES, v1 = r1 < N_NODES;
    const float* Ar0 = A + (size_t)r0 * lda;
    const float* Ar1 = A + (size_t)r1 * lda;

    for (int ks = 0; ks < KSTEPS; ks++) {
        int k0 = ks * 8;
        int c0 = k0 + tig, c1 = k0 + tig + 4;
        float f0 = (v0 && c0 < DIM) ? Ar0[c0] : 0.f;
        float f1 = (v1 && c0 < DIM) ? Ar1[c0] : 0.f;
        float f2 = (v0 && c1 < DIM) ? Ar0[c1] : 0.f;
        float f3 = (v1 && c1 < DIM) ? Ar1[c1] : 0.f;
        unsigned a0 = f2tf32(f0), a1 = f2tf32(f1), a2 = f2tf32(f2), a3 = f2tf32(f3);

        #pragma unroll
        for (int nt = 0; nt < NTILES; nt++) {
            unsigned b0 = Ws[(k0 + tig) * WSTRIDE + nt * 8 + gid];
            unsigned b1 = Ws[(k0 + tig + 4) * WSTRIDE + nt * 8 + gid];
            asm volatile(
                "mma.sync.aligned.m16n8k8.row.col.f32.tf32.tf32.f32 "
                "{%0,%1,%2,%3}, {%4,%5,%6,%7}, {%8,%9}, {%0,%1,%2,%3};"
                : "+f"(acc[nt][0]), "+f"(acc[nt][1]),
                  "+f"(acc[nt][2]), "+f"(acc[nt][3])
                : "r"(a0), "r"(a1), "r"(a2), "r"(a3), "r"(b0), "r"(b1));
        }
    }

    // cols 133..135 in Ws are zero -> acc there is exactly 0: store unguarded on n
    #pragma unroll
    for (int nt = 0; nt < NTILES; nt++) {
        int n0 = nt * 8 + tig * 2;          // <= 135 < HP
        if (v0) {
            g_h[(size_t)r0 * HP + n0]     = acc[nt][0];
            g_h[(size_t)r0 * HP + n0 + 1] = acc[nt][1];
        }
        if (v1) {
            g_h[(size_t)r1 * HP + n0]     = acc[nt][2];
            g_h[(size_t)r1 * HP + n0 + 1] = acc[nt][3];
        }
    }
}

// -------- aggregation: g_t = BN(relu(scatter(norm * g_h[src]) + b)) -----------
// one warp per destination node; float4 gathers; zero atomics
__global__ __launch_bounds__(256) void agg_kernel(const float* __restrict__ b,
                                                  const float* __restrict__ gam,
                                                  const float* __restrict__ bet,
                                                  const float* __restrict__ rm,
                                                  const float* __restrict__ rv) {
    int node = (blockIdx.x * blockDim.x + threadIdx.x) >> 5;
    int lane = threadIdx.x & 31;
    if (node >= N_NODES) return;
    const float4* __restrict__ h4 = (const float4*)g_h;

    float di = g_dinv[node];
    int start = g_off[node];
    int end = (node + 1 < N_NODES) ? g_off[node + 1] : N_EDGES;

    // self loop init (weight dinv^2)
    float sw = di * di;
    const float4* hn = h4 + (size_t)node * (HP / 4);
    float4 v = hn[lane];
    float4 a0 = make_float4(sw * v.x, sw * v.y, sw * v.z, sw * v.w);
    float4 a1 = make_float4(0.f, 0.f, 0.f, 0.f);
    if (lane < 2) {
        float4 v2 = hn[32 + lane];
        a1 = make_float4(sw * v2.x, sw * v2.y, sw * v2.z, sw * v2.w);
    }

    for (int j = start; j < end; j += 32) {
        int jj = j + lane;
        int2 e2 = (jj < end) ? g_edge[jj] : make_int2(0, 0);
        int cnt = min(32, end - j);
        for (int l = 0; l < cnt; l++) {
            int src = __shfl_sync(0xFFFFFFFFu, e2.x, l);
            float w = __int_as_float(__shfl_sync(0xFFFFFFFFu, e2.y, l)) * di;
            const float4* hr = h4 + (size_t)src * (HP / 4);
            float4 u = hr[lane];
            a0.x = fmaf(w, u.x, a0.x);
            a0.y = fmaf(w, u.y, a0.y);
            a0.z = fmaf(w, u.z, a0.z);
            a0.w = fmaf(w, u.w, a0.w);
            if (lane < 2) {
                float4 u2 = hr[32 + lane];
                a1.x = fmaf(w, u2.x, a1.x);
                a1.y = fmaf(w, u2.y, a1.y);
                a1.z = fmaf(w, u2.z, a1.z);
                a1.w = fmaf(w, u2.w, a1.w);
            }
        }
    }

    // epilogue: bias + ReLU + BN, float4 store (pad cols written as 0)
    float* arr0 = &a0.x;
    float* arr1 = &a1.x;
    {
        int d0 = lane * 4;                      // 0..124 (all < 133)
        float4 o;
        float* op = &o.x;
        #pragma unroll
        for (int q = 0; q < 4; q++) {
            int d = d0 + q;
            float val = arr0[q] + b[d];
            val = fmaxf(val, 0.f);
            op[q] = (val - rm[d]) * rsqrtf(rv[d] + EPS) * gam[d] + bet[d];
        }
        ((float4*)g_t)[(size_t)node * (HP / 4) + lane] = o;
    }
    if (lane < 2) {
        int d0 = 128 + lane * 4;               // 128..135
        float4 o;
        float* op = &o.x;
        #pragma unroll
        for (int q = 0; q < 4; q++) {
            int d = d0 + q;
            if (d < DIM) {
                float val = arr1[q] + b[d];
                val = fmaxf(val, 0.f);
                op[q] = (val - rm[d]) * rsqrtf(rv[d] + EPS) * gam[d] + bet[d];
            } else {
                op[q] = 0.f;
            }
        }
        ((float4*)g_t)[(size_t)node * (HP / 4) + 32 + lane] = o;
    }
}

// ---------------- pooling: one warp per graph, no atomics ----------------
__global__ __launch_bounds__(256) void pool_kernel(float* __restrict__ out) {
    int g = (blockIdx.x * blockDim.x + threadIdx.x) >> 5;
    int lane = threadIdx.x & 31;
    if (g >= N_GRAPHS) return;
    int s = g_goff[g], e = g_goff[g + 1];
    const float4* __restrict__ t4 = (const float4*)g_t;
    float4 a0 = make_float4(0.f, 0.f, 0.f, 0.f);
    float4 a1 = make_float4(0.f, 0.f, 0.f, 0.f);
    for (int n = s; n < e; n++) {
        const float4* r = t4 + (size_t)n * (HP / 4);
        float4 u = r[lane];
        a0.x += u.x; a0.y += u.y; a0.z += u.z; a0.w += u.w;
        if (lane < 2) {
            float4 u2 = r[32 + lane];
            a1.x += u2.x; a1.y += u2.y; a1.z += u2.z; a1.w += u2.w;
        }
    }
    float inv = 1.f / fmaxf((float)(e - s), 1.f);
    float* arr0 = &a0.x;
    float* arr1 = &a1.x;
    int d0 = lane * 4;
    #pragma unroll
    for (int q = 0; q < 4; q++) out[g * DIM + d0 + q] = arr0[q] * inv;
    if (lane < 2) {
        #pragma unroll
        for (int q = 0; q < 4; q++) {
            int d = 128 + lane * 4 + q;
            if (d < DIM) out[g * DIM + d] = arr1[q] * inv;
        }
    }
}

// ---------------- launch ----------------
extern "C" void kernel_launch(void* const* d_in, const int* in_sizes, int n_in,
                              void* d_out, int out_size) {
    const float* x     = (const float*)d_in[0];
    const int*   ei    = (const int*)d_in[1];   // [2, E] int32
    const int*   batch = (const int*)d_in[2];   // [N] int32
    const float* W1 = (const float*)d_in[3];
    const float* b1 = (const float*)d_in[4];
    const float* W2 = (const float*)d_in[5];
    const float* b2 = (const float*)d_in[6];
    const float* g1 = (const float*)d_in[7];
    const float* be1 = (const float*)d_in[8];
    const float* rm1 = (const float*)d_in[9];
    const float* rv1 = (const float*)d_in[10];
    const float* g2 = (const float*)d_in[11];
    const float* be2 = (const float*)d_in[12];
    const float* rm2 = (const float*)d_in[13];
    const float* rv2 = (const float*)d_in[14];
    float* out = (float*)d_out;

    const int* row = ei;            // first E entries
    const int* col = ei + N_EDGES;  // second E entries

    const int SMEM_W = WSTRIDE * WSTRIDE * 4;   // 73984 bytes
    cudaFuncSetAttribute(gemm_tc_kernel,
                         cudaFuncAttributeMaxDynamicSharedMemorySize, SMEM_W);

    // 1. CSR build (+ per-graph ranges for pooling)
    prep_kernel<<<NB, 256>>>(batch);
    hist_kernel<<<2048, 256>>>(col);
    reduce_kernel<<<NB, 256>>>();
    scan_apply_kernel<<<NB, 256>>>();
    scatter_kernel<<<2048, 256>>>(row, col);

    // 2. layer 1: tf32 GEMM -> aggregate (+bias, ReLU, BN fused)
    gemm_tc_kernel<<<(N_NODES + 63) / 64, 128, SMEM_W>>>(x, W1, 0);
    agg_kernel<<<(N_NODES * 32 + 255) / 256, 256>>>(b1, g1, be1, rm1, rv1);

    // 3. layer 2 (A comes from g_t via flag)
    gemm_tc_kernel<<<(N_NODES + 63) / 64, 128, SMEM_W>>>(x, W2, 1);
    agg_kernel<<<(N_NODES * 32 + 255) / 256, 256>>>(b2, g2, be2, rm2, rv2);

    // 4. global mean pool (sorted batch -> contiguous ranges, no atomics)
    pool_kernel<<<(N_GRAPHS * 32 + 255) / 256, 256>>>(out);
}

// round 9
// speedup vs baseline: 1.6517x; 1.6517x over previous
#include <cuda_runtime.h>
#include <cuda_fp16.h>
#include <math.h>

#define N_NODES 50000
#define N_EDGES 1600000
#define N_GRAPHS 2048
#define DIM 133
#define HPH 136          // padded halves per feature row (272 B, 16B aligned)
#define H2 68            // half2 per row
#define EPS 1e-5f
#define NB 196           // ceil(50000/256)
#define WSTRIDE 136
#define KSTEPS 17        // 17*8 = 136 >= 133
#define NTILES 17

// ---------------- scratch (device globals; no allocation allowed) ----------------
__device__ __half g_h[(size_t)N_NODES * HPH];  // GEMM output (fp16, padded)
__device__ __half g_t[(size_t)N_NODES * HPH];  // layer output (fp16, padded)
__device__ int    g_cnt[N_NODES];              // in-degree histogram (no self loop)
__device__ int    g_off[N_NODES];              // CSR row offsets
__device__ int    g_cursor[N_NODES];           // scatter cursors
__device__ int2   g_edge[N_EDGES];             // CSR: {src, bitcast(dinv[src])}
__device__ float  g_dinv[N_NODES];             // rsqrt(deg+1)
__device__ int    g_bsum[NB];                  // per-block histogram sums
__device__ int    g_goff[N_GRAPHS + 1];        // per-graph node ranges (batch sorted)

// ---------------- preprocessing ----------------
__global__ __launch_bounds__(256) void prep_kernel(const int* __restrict__ batch) {
    int i = blockIdx.x * blockDim.x + threadIdx.x;
    if (i >= N_NODES) return;
    g_cnt[i] = 0;
    int b = batch[i];
    int prev = (i == 0) ? -1 : batch[i - 1];
    for (int g = prev + 1; g <= b; g++) g_goff[g] = i;
    if (i == N_NODES - 1) {
        for (int g = b + 1; g <= N_GRAPHS; g++) g_goff[g] = N_NODES;
    }
}

__global__ void hist_kernel(const int* __restrict__ col) {
    for (int e = blockIdx.x * blockDim.x + threadIdx.x; e < N_EDGES;
         e += gridDim.x * blockDim.x) {
        atomicAdd(&g_cnt[col[e]], 1);
    }
}

__global__ __launch_bounds__(256) void reduce_kernel() {
    int i = blockIdx.x * 256 + threadIdx.x;
    int v = (i < N_NODES) ? g_cnt[i] : 0;
    #pragma unroll
    for (int off = 16; off > 0; off >>= 1)
        v += __shfl_down_sync(0xFFFFFFFFu, v, off);
    __shared__ int ws[8];
    int lane = threadIdx.x & 31, w = threadIdx.x >> 5;
    if (lane == 0) ws[w] = v;
    __syncthreads();
    if (threadIdx.x == 0) {
        int s = 0;
        #pragma unroll
        for (int j = 0; j < 8; j++) s += ws[j];
        g_bsum[blockIdx.x] = s;
    }
}

// block-local scan; each block reduces its own prefix of g_bsum inline
__global__ __launch_bounds__(256) void scan_apply_kernel() {
    int t = threadIdx.x;
    int lane = t & 31, w = t >> 5;

    int pv = (t < blockIdx.x) ? g_bsum[t] : 0;
    #pragma unroll
    for (int off = 16; off > 0; off >>= 1)
        pv += __shfl_down_sync(0xFFFFFFFFu, pv, off);
    __shared__ int wred[8];
    __shared__ int pref;
    if (lane == 0) wred[w] = pv;
    __syncthreads();
    if (t == 0) {
        int s = 0;
        #pragma unroll
        for (int j = 0; j < 8; j++) s += wred[j];
        pref = s;
    }

    int i = blockIdx.x * 256 + t;
    int v = (i < N_NODES) ? g_cnt[i] : 0;
    int s = v;
    #pragma unroll
    for (int d = 1; d < 32; d <<= 1) {
        int tt = __shfl_up_sync(0xFFFFFFFFu, s, d);
        if (lane >= d) s += tt;
    }
    __shared__ int ws[8];
    __shared__ int wo[8];
    if (lane == 31) ws[w] = s;
    __syncthreads();
    if (t == 0) {
        int r = 0;
        #pragma unroll
        for (int j = 0; j < 8; j++) { wo[j] = r; r += ws[j]; }
    }
    __syncthreads();
    if (i < N_NODES) {
        int excl = pref + wo[w] + (s - v);
        g_off[i] = excl;
        g_cursor[i] = excl;
        g_dinv[i] = rsqrtf((float)(v + 1));   // +1 self loop
    }
}

__global__ void scatter_kernel(const int* __restrict__ row,
                               const int* __restrict__ col) {
    for (int e = blockIdx.x * blockDim.x + threadIdx.x; e < N_EDGES;
         e += gridDim.x * blockDim.x) {
        int c = col[e];
        int r = row[e];
        int p = atomicAdd(&g_cursor[c], 1);
        g_edge[p] = make_int2(r, __float_as_int(g_dinv[r]));
    }
}

// ---------- tf32 tensor-core GEMM: g_h[M,:](fp16) = A[M,133] @ W[133,133] ----------
__device__ __forceinline__ unsigned f2tf32(float f) {
    unsigned u;
    asm("cvt.rna.tf32.f32 %0, %1;" : "=r"(u) : "f"(f));
    return u;
}

__global__ __launch_bounds__(128) void gemm_tc_kernel(const float* __restrict__ A_ext,
                                                      const float* __restrict__ W,
                                                      int use_gt) {
    extern __shared__ unsigned Ws[];   // WSTRIDE * WSTRIDE tf32 words
    int tid = threadIdx.x;

    for (int idx = tid; idx < WSTRIDE * WSTRIDE; idx += 128) {
        int k = idx / WSTRIDE, n = idx - k * WSTRIDE;
        float v = (k < DIM && n < DIM) ? W[k * DIM + n] : 0.f;
        Ws[idx] = f2tf32(v);
    }
    __syncthreads();

    int warp = tid >> 5, lane = tid & 31;
    int gid = lane >> 2;    // 0..7
    int tig = lane & 3;     // 0..3
    int m0 = blockIdx.x * 64 + warp * 16;

    float acc[NTILES][4];
    #pragma unroll
    for (int n = 0; n < NTILES; n++) {
        acc[n][0] = acc[n][1] = acc[n][2] = acc[n][3] = 0.f;
    }

    int r0 = m0 + gid;
    int r1 = m0 + gid + 8;
    bool v0 = r0 < N_NODES, v1 = r1 < N_NODES;
    const float* Ar0 = A_ext + (size_t)r0 * DIM;
    const float* Ar1 = A_ext + (size_t)r1 * DIM;
    const __half* At0 = g_t + (size_t)r0 * HPH;
    const __half* At1 = g_t + (size_t)r1 * HPH;

    for (int ks = 0; ks < KSTEPS; ks++) {
        int k0 = ks * 8;
        int c0 = k0 + tig, c1 = k0 + tig + 4;
        float f0, f1, f2, f3;
        if (use_gt) {
            f0 = (v0 && c0 < DIM) ? __half2float(At0[c0]) : 0.f;
            f1 = (v1 && c0 < DIM) ? __half2float(At1[c0]) : 0.f;
            f2 = (v0 && c1 < DIM) ? __half2float(At0[c1]) : 0.f;
            f3 = (v1 && c1 < DIM) ? __half2float(At1[c1]) : 0.f;
        } else {
            f0 = (v0 && c0 < DIM) ? Ar0[c0] : 0.f;
            f1 = (v1 && c0 < DIM) ? Ar1[c0] : 0.f;
            f2 = (v0 && c1 < DIM) ? Ar0[c1] : 0.f;
            f3 = (v1 && c1 < DIM) ? Ar1[c1] : 0.f;
        }
        unsigned a0 = f2tf32(f0), a1 = f2tf32(f1), a2 = f2tf32(f2), a3 = f2tf32(f3);

        #pragma unroll
        for (int nt = 0; nt < NTILES; nt++) {
            unsigned b0 = Ws[(k0 + tig) * WSTRIDE + nt * 8 + gid];
            unsigned b1 = Ws[(k0 + tig + 4) * WSTRIDE + nt * 8 + gid];
            asm volatile(
                "mma.sync.aligned.m16n8k8.row.col.f32.tf32.tf32.f32 "
                "{%0,%1,%2,%3}, {%4,%5,%6,%7}, {%8,%9}, {%0,%1,%2,%3};"
                : "+f"(acc[nt][0]), "+f"(acc[nt][1]),
                  "+f"(acc[nt][2]), "+f"(acc[nt][3])
                : "r"(a0), "r"(a1), "r"(a2), "r"(a3), "r"(b0), "r"(b1));
        }
    }

    // adjacent accumulator pair -> one half2 store; pad cols (133..135) are 0
    __half2* H2p = (__half2*)g_h;
    #pragma unroll
    for (int nt = 0; nt < NTILES; nt++) {
        int h2i = nt * 4 + tig;             // 0..67 (full row coverage)
        if (v0) H2p[(size_t)r0 * H2 + h2i] = __floats2half2_rn(acc[nt][0], acc[nt][1]);
        if (v1) H2p[(size_t)r1 * H2 + h2i] = __floats2half2_rn(acc[nt][2], acc[nt][3]);
    }
}

// -------- aggregation: g_t = BN(relu(scatter(norm * g_h[src]) + b)) -----------
// one warp per destination node; scalar half2 gathers (no LDG.128 replays)
__global__ __launch_bounds__(256) void agg_kernel(const float* __restrict__ b,
                                                  const float* __restrict__ gam,
                                                  const float* __restrict__ bet,
                                                  const float* __restrict__ rm,
                                                  const float* __restrict__ rv) {
    int node = (blockIdx.x * blockDim.x + threadIdx.x) >> 5;
    int lane = threadIdx.x & 31;
    if (node >= N_NODES) return;
    const __half2* __restrict__ h2 = (const __half2*)g_h;

    float di = g_dinv[node];
    int start = g_off[node];
    int end = (node + 1 < N_NODES) ? g_off[node + 1] : N_EDGES;

    // self loop init (weight dinv^2)
    float sw = di * di;
    const __half2* hn = h2 + (size_t)node * H2;
    float2 a0, a1, a2;
    {
        float2 p = __half22float2(hn[lane]);
        float2 q = __half22float2(hn[32 + lane]);
        a0 = make_float2(sw * p.x, sw * p.y);
        a1 = make_float2(sw * q.x, sw * q.y);
        a2 = make_float2(0.f, 0.f);
        if (lane < 3) {
            float2 r = __half22float2(hn[64 + lane]);
            a2 = make_float2(sw * r.x, sw * r.y);
        }
    }

    for (int j = start; j < end; j += 32) {
        int jj = j + lane;
        int2 e2 = (jj < end) ? g_edge[jj] : make_int2(0, 0);
        int cnt = min(32, end - j);
        for (int l = 0; l < cnt; l++) {
            int src = __shfl_sync(0xFFFFFFFFu, e2.x, l);
            float w = __int_as_float(__shfl_sync(0xFFFFFFFFu, e2.y, l)) * di;
            const __half2* hr = h2 + (size_t)src * H2;
            float2 p = __half22float2(hr[lane]);
            float2 q = __half22float2(hr[32 + lane]);
            a0.x = fmaf(w, p.x, a0.x);
            a0.y = fmaf(w, p.y, a0.y);
            a1.x = fmaf(w, q.x, a1.x);
            a1.y = fmaf(w, q.y, a1.y);
            if (lane < 3) {
                float2 r = __half22float2(hr[64 + lane]);
                a2.x = fmaf(w, r.x, a2.x);
                a2.y = fmaf(w, r.y, a2.y);
            }
        }
    }

    // epilogue: bias + ReLU + BN -> fp16 store
    __half2* t2 = (__half2*)g_t + (size_t)node * H2;
    {
        int d = 2 * lane;                          // 0..62 -> both valid
        float vx = fmaxf(a0.x + b[d], 0.f);
        float vy = fmaxf(a0.y + b[d + 1], 0.f);
        vx = (vx - rm[d]) * rsqrtf(rv[d] + EPS) * gam[d] + bet[d];
        vy = (vy - rm[d + 1]) * rsqrtf(rv[d + 1] + EPS) * gam[d + 1] + bet[d + 1];
        t2[lane] = __floats2half2_rn(vx, vy);
    }
    {
        int d = 64 + 2 * lane;                     // 64..126 -> both valid
        float vx = fmaxf(a1.x + b[d], 0.f);
        float vy = fmaxf(a1.y + b[d + 1], 0.f);
        vx = (vx - rm[d]) * rsqrtf(rv[d] + EPS) * gam[d] + bet[d];
        vy = (vy - rm[d + 1]) * rsqrtf(rv[d + 1] + EPS) * gam[d + 1] + bet[d + 1];
        t2[32 + lane] = __floats2half2_rn(vx, vy);
    }
    if (lane < 3) {
        int d = 128 + 2 * lane;                    // 128,130,132
        float vx = fmaxf(a2.x + b[d], 0.f);
        vx = (vx - rm[d]) * rsqrtf(rv[d] + EPS) * gam[d] + bet[d];
        float vy = 0.f;
        if (d + 1 < DIM) {
            vy = fmaxf(a2.y + b[d + 1], 0.f);
            vy = (vy - rm[d + 1]) * rsqrtf(rv[d + 1] + EPS) * gam[d + 1] + bet[d + 1];
        }
        t2[64 + lane] = __floats2half2_rn(vx, vy);
    }
}

// ---------------- pooling: one warp per graph, no atomics ----------------
__global__ __launch_bounds__(256) void pool_kernel(float* __restrict__ out) {
    int g = (blockIdx.x * blockDim.x + threadIdx.x) >> 5;
    int lane = threadIdx.x & 31;
    if (g >= N_GRAPHS) return;
    int s = g_goff[g], e = g_goff[g + 1];
    const __half2* __restrict__ t2 = (const __half2*)g_t;
    float2 a0 = make_float2(0.f, 0.f);
    float2 a1 = make_float2(0.f, 0.f);
    float2 a2 = make_float2(0.f, 0.f);
    for (int n = s; n < e; n++) {
        const __half2* r = t2 + (size_t)n * H2;
        float2 p = __half22float2(r[lane]);
        float2 q = __half22float2(r[32 + lane]);
        a0.x += p.x; a0.y += p.y;
        a1.x += q.x; a1.y += q.y;
        if (lane < 3) {
            float2 rr = __half22float2(r[64 + lane]);
            a2.x += rr.x; a2.y += rr.y;
        }
    }
    float inv = 1.f / fmaxf((float)(e - s), 1.f);
    int d0 = 2 * lane;
    out[g * DIM + d0]     = a0.x * inv;
    out[g * DIM + d0 + 1] = a0.y * inv;
    out[g * DIM + 64 + d0]     = a1.x * inv;
    out[g * DIM + 64 + d0 + 1] = a1.y * inv;
    if (lane < 3) {
        int d = 128 + 2 * lane;
        out[g * DIM + d] = a2.x * inv;
        if (d + 1 < DIM) out[g * DIM + d + 1] = a2.y * inv;
    }
}

// ---------------- launch ----------------
extern "C" void kernel_launch(void* const* d_in, const int* in_sizes, int n_in,
                              void* d_out, int out_size) {
    const float* x     = (const float*)d_in[0];
    const int*   ei    = (const int*)d_in[1];   // [2, E] int32
    const int*   batch = (const int*)d_in[2];   // [N] int32
    const float* W1 = (const float*)d_in[3];
    const float* b1 = (const float*)d_in[4];
    const float* W2 = (const float*)d_in[5];
    const float* b2 = (const float*)d_in[6];
    const float* g1 = (const float*)d_in[7];
    const float* be1 = (const float*)d_in[8];
    const float* rm1 = (const float*)d_in[9];
    const float* rv1 = (const float*)d_in[10];
    const float* g2 = (const float*)d_in[11];
    const float* be2 = (const float*)d_in[12];
    const float* rm2 = (const float*)d_in[13];
    const float* rv2 = (const float*)d_in[14];
    float* out = (float*)d_out;

    const int* row = ei;            // first E entries
    const int* col = ei + N_EDGES;  // second E entries

    const int SMEM_W = WSTRIDE * WSTRIDE * 4;   // 73984 bytes
    cudaFuncSetAttribute(gemm_tc_kernel,
                         cudaFuncAttributeMaxDynamicSharedMemorySize, SMEM_W);

    // 1. CSR build (+ per-graph ranges for pooling)
    prep_kernel<<<NB, 256>>>(batch);
    hist_kernel<<<2048, 256>>>(col);
    reduce_kernel<<<NB, 256>>>();
    scan_apply_kernel<<<NB, 256>>>();
    scatter_kernel<<<2048, 256>>>(row, col);

    // 2. layer 1: tf32 GEMM -> aggregate (+bias, ReLU, BN fused)
    gemm_tc_kernel<<<(N_NODES + 63) / 64, 128, SMEM_W>>>(x, W1, 0);
    agg_kernel<<<(N_NODES * 32 + 255) / 256, 256>>>(b1, g1, be1, rm1, rv1);

    // 3. layer 2 (A comes from g_t, fp16)
    gemm_tc_kernel<<<(N_NODES + 63) / 64, 128, SMEM_W>>>(x, W2, 1);
    agg_kernel<<<(N_NODES * 32 + 255) / 256, 256>>>(b2, g2, be2, rm2, rv2);

    // 4. global mean pool (sorted batch -> contiguous ranges, no atomics)
    pool_kernel<<<(N_GRAPHS * 32 + 255) / 256, 256>>>(out);
}

// round 10
// speedup vs baseline: 1.8660x; 1.1297x over previous
#include <cuda_runtime.h>
#include <cuda_fp16.h>
#include <math.h>

#define N_NODES 50000
#define N_EDGES 1600000
#define N_GRAPHS 2048
#define DIM 133
#define HPH 136          // padded halves per feature row (272 B, 16B aligned)
#define H2 68            // half2 per row
#define EPS 1e-5f
#define NB 196           // ceil(50000/256)
#define WSTRIDE 136
#define KSTEPS 17        // 17*8 = 136 >= 133
#define NTILES 17

// ---------------- scratch (device globals; no allocation allowed) ----------------
__device__ __half g_h[(size_t)N_NODES * HPH];  // GEMM output (fp16, padded)
__device__ __half g_t[(size_t)N_NODES * HPH];  // layer output (fp16, padded)
__device__ int    g_cnt[N_NODES];              // in-degree histogram (no self loop)
__device__ int    g_off[N_NODES];              // CSR row offsets
__device__ int    g_cursor[N_NODES];           // scatter cursors
__device__ int2   g_edge[N_EDGES];             // CSR: {src, bitcast(norm=dinv[s]*dinv[d])}
__device__ float  g_dinv[N_NODES];             // rsqrt(deg+1)
__device__ int    g_bsum[NB];                  // per-block histogram sums
__device__ int    g_goff[N_GRAPHS + 1];        // per-graph node ranges (batch sorted)
__device__ float  g_sc[2][HPH];                // BN scale  per layer (gam*rsqrt(rv+eps))
__device__ float  g_sh[2][HPH];                // BN shift  per layer (bet - rm*sc)

// ---------------- preprocessing ----------------
// zero histogram + per-graph ranges + BN affine precompute (one launch)
__global__ __launch_bounds__(256) void prep_kernel(const int* __restrict__ batch,
                                                   const float* __restrict__ g1,
                                                   const float* __restrict__ be1,
                                                   const float* __restrict__ rm1,
                                                   const float* __restrict__ rv1,
                                                   const float* __restrict__ g2,
                                                   const float* __restrict__ be2,
                                                   const float* __restrict__ rm2,
                                                   const float* __restrict__ rv2) {
    int i = blockIdx.x * blockDim.x + threadIdx.x;
    if (blockIdx.x == 0 && threadIdx.x < HPH) {
        int d = threadIdx.x;
        if (d < DIM) {
            float s1 = g1[d] * rsqrtf(rv1[d] + EPS);
            g_sc[0][d] = s1;
            g_sh[0][d] = be1[d] - rm1[d] * s1;
            float s2 = g2[d] * rsqrtf(rv2[d] + EPS);
            g_sc[1][d] = s2;
            g_sh[1][d] = be2[d] - rm2[d] * s2;
        } else {
            g_sc[0][d] = 0.f; g_sh[0][d] = 0.f;
            g_sc[1][d] = 0.f; g_sh[1][d] = 0.f;
        }
    }
    if (i >= N_NODES) return;
    g_cnt[i] = 0;
    int b = batch[i];
    int prev = (i == 0) ? -1 : batch[i - 1];
    for (int g = prev + 1; g <= b; g++) g_goff[g] = i;
    if (i == N_NODES - 1) {
        for (int g = b + 1; g <= N_GRAPHS; g++) g_goff[g] = N_NODES;
    }
}

__global__ void hist_kernel(const int* __restrict__ col) {
    for (int e = blockIdx.x * blockDim.x + threadIdx.x; e < N_EDGES;
         e += gridDim.x * blockDim.x) {
        atomicAdd(&g_cnt[col[e]], 1);
    }
}

__global__ __launch_bounds__(256) void reduce_kernel() {
    int i = blockIdx.x * 256 + threadIdx.x;
    int v = (i < N_NODES) ? g_cnt[i] : 0;
    #pragma unroll
    for (int off = 16; off > 0; off >>= 1)
        v += __shfl_down_sync(0xFFFFFFFFu, v, off);
    __shared__ int ws[8];
    int lane = threadIdx.x & 31, w = threadIdx.x >> 5;
    if (lane == 0) ws[w] = v;
    __syncthreads();
    if (threadIdx.x == 0) {
        int s = 0;
        #pragma unroll
        for (int j = 0; j < 8; j++) s += ws[j];
        g_bsum[blockIdx.x] = s;
    }
}

// block-local scan; each block reduces its own prefix of g_bsum inline
__global__ __launch_bounds__(256) void scan_apply_kernel() {
    int t = threadIdx.x;
    int lane = t & 31, w = t >> 5;

    int pv = (t < blockIdx.x) ? g_bsum[t] : 0;
    #pragma unroll
    for (int off = 16; off > 0; off >>= 1)
        pv += __shfl_down_sync(0xFFFFFFFFu, pv, off);
    __shared__ int wred[8];
    __shared__ int pref;
    if (lane == 0) wred[w] = pv;
    __syncthreads();
    if (t == 0) {
        int s = 0;
        #pragma unroll
        for (int j = 0; j < 8; j++) s += wred[j];
        pref = s;
    }

    int i = blockIdx.x * 256 + t;
    int v = (i < N_NODES) ? g_cnt[i] : 0;
    int s = v;
    #pragma unroll
    for (int d = 1; d < 32; d <<= 1) {
        int tt = __shfl_up_sync(0xFFFFFFFFu, s, d);
        if (lane >= d) s += tt;
    }
    __shared__ int ws[8];
    __shared__ int wo[8];
    if (lane == 31) ws[w] = s;
    __syncthreads();
    if (t == 0) {
        int r = 0;
        #pragma unroll
        for (int j = 0; j < 8; j++) { wo[j] = r; r += ws[j]; }
    }
    __syncthreads();
    if (i < N_NODES) {
        int excl = pref + wo[w] + (s - v);
        g_off[i] = excl;
        g_cursor[i] = excl;
        g_dinv[i] = rsqrtf((float)(v + 1));   // +1 self loop
    }
}

// scatter: CSR by destination; pack (src, full norm) per edge
__global__ void scatter_kernel(const int* __restrict__ row,
                               const int* __restrict__ col) {
    for (int e = blockIdx.x * blockDim.x + threadIdx.x; e < N_EDGES;
         e += gridDim.x * blockDim.x) {
        int c = col[e];
        int r = row[e];
        int p = atomicAdd(&g_cursor[c], 1);
        float norm = g_dinv[r] * g_dinv[c];
        g_edge[p] = make_int2(r, __float_as_int(norm));
    }
}

// ---------- tf32 tensor-core GEMM: g_h[M,:](fp16) = A[M,133] @ W[133,133] ----------
__device__ __forceinline__ unsigned f2tf32(float f) {
    unsigned u;
    asm("cvt.rna.tf32.f32 %0, %1;" : "=r"(u) : "f"(f));
    return u;
}

__global__ __launch_bounds__(128) void gemm_tc_kernel(const float* __restrict__ A_ext,
                                                      const float* __restrict__ W,
                                                      int use_gt) {
    extern __shared__ unsigned Ws[];   // WSTRIDE * WSTRIDE tf32 words
    int tid = threadIdx.x;

    for (int idx = tid; idx < WSTRIDE * WSTRIDE; idx += 128) {
        int k = idx / WSTRIDE, n = idx - k * WSTRIDE;
        float v = (k < DIM && n < DIM) ? W[k * DIM + n] : 0.f;
        Ws[idx] = f2tf32(v);
    }
    __syncthreads();

    int warp = tid >> 5, lane = tid & 31;
    int gid = lane >> 2;    // 0..7
    int tig = lane & 3;     // 0..3
    int m0 = blockIdx.x * 64 + warp * 16;

    float acc[NTILES][4];
    #pragma unroll
    for (int n = 0; n < NTILES; n++) {
        acc[n][0] = acc[n][1] = acc[n][2] = acc[n][3] = 0.f;
    }

    int r0 = m0 + gid;
    int r1 = m0 + gid + 8;
    bool v0 = r0 < N_NODES, v1 = r1 < N_NODES;
    const float* Ar0 = A_ext + (size_t)r0 * DIM;
    const float* Ar1 = A_ext + (size_t)r1 * DIM;
    const __half* At0 = g_t + (size_t)r0 * HPH;
    const __half* At1 = g_t + (size_t)r1 * HPH;

    for (int ks = 0; ks < KSTEPS; ks++) {
        int k0 = ks * 8;
        int c0 = k0 + tig, c1 = k0 + tig + 4;
        float f0, f1, f2, f3;
        if (use_gt) {
            f0 = (v0 && c0 < DIM) ? __half2float(At0[c0]) : 0.f;
            f1 = (v1 && c0 < DIM) ? __half2float(At1[c0]) : 0.f;
            f2 = (v0 && c1 < DIM) ? __half2float(At0[c1]) : 0.f;
            f3 = (v1 && c1 < DIM) ? __half2float(At1[c1]) : 0.f;
        } else {
            f0 = (v0 && c0 < DIM) ? Ar0[c0] : 0.f;
            f1 = (v1 && c0 < DIM) ? Ar1[c0] : 0.f;
            f2 = (v0 && c1 < DIM) ? Ar0[c1] : 0.f;
            f3 = (v1 && c1 < DIM) ? Ar1[c1] : 0.f;
        }
        unsigned a0 = f2tf32(f0), a1 = f2tf32(f1), a2 = f2tf32(f2), a3 = f2tf32(f3);

        #pragma unroll
        for (int nt = 0; nt < NTILES; nt++) {
            unsigned b0 = Ws[(k0 + tig) * WSTRIDE + nt * 8 + gid];
            unsigned b1 = Ws[(k0 + tig + 4) * WSTRIDE + nt * 8 + gid];
            asm volatile(
                "mma.sync.aligned.m16n8k8.row.col.f32.tf32.tf32.f32 "
                "{%0,%1,%2,%3}, {%4,%5,%6,%7}, {%8,%9}, {%0,%1,%2,%3};"
                : "+f"(acc[nt][0]), "+f"(acc[nt][1]),
                  "+f"(acc[nt][2]), "+f"(acc[nt][3])
                : "r"(a0), "r"(a1), "r"(a2), "r"(a3), "r"(b0), "r"(b1));
        }
    }

    __half2* H2p = (__half2*)g_h;
    #pragma unroll
    for (int nt = 0; nt < NTILES; nt++) {
        int h2i = nt * 4 + tig;             // 0..67 (full row coverage)
        if (v0) H2p[(size_t)r0 * H2 + h2i] = __floats2half2_rn(acc[nt][0], acc[nt][1]);
        if (v1) H2p[(size_t)r1 * H2 + h2i] = __floats2half2_rn(acc[nt][2], acc[nt][3]);
    }
}

// -------- aggregation: g_t = BN(relu(scatter(norm * g_h[src]) + b)) -----------
// one warp per node; batched edge metadata via shfl; unroll-4 gathers for MLP;
// epilogue uses precomputed BN affine (no MUFU)
__global__ __launch_bounds__(256) void agg_kernel(const float* __restrict__ b,
                                                  int layer) {
    int node = (blockIdx.x * blockDim.x + threadIdx.x) >> 5;
    int lane = threadIdx.x & 31;
    if (node >= N_NODES) return;
    const __half2* __restrict__ h2 = (const __half2*)g_h;

    float di = g_dinv[node];
    int start = g_off[node];
    int end = (node + 1 < N_NODES) ? g_off[node + 1] : N_EDGES;

    // self loop init (weight dinv^2)
    float sw = di * di;
    const __half2* hn = h2 + (size_t)node * H2;
    float2 a0, a1, a2;
    {
        float2 p = __half22float2(hn[lane]);
        float2 q = __half22float2(hn[32 + lane]);
        a0 = make_float2(sw * p.x, sw * p.y);
        a1 = make_float2(sw * q.x, sw * q.y);
        a2 = make_float2(0.f, 0.f);
        if (lane < 3) {
            float2 r = __half22float2(hn[64 + lane]);
            a2 = make_float2(sw * r.x, sw * r.y);
        }
    }

    bool tl = lane < 3;
    for (int j = start; j < end; j += 32) {
        int jj = j + lane;
        int2 e2 = (jj < end) ? g_edge[jj] : make_int2(0, 0);
        int cnt = min(32, end - j);
        int l = 0;
        for (; l + 4 <= cnt; l += 4) {
            int s0 = __shfl_sync(0xFFFFFFFFu, e2.x, l);
            int s1 = __shfl_sync(0xFFFFFFFFu, e2.x, l + 1);
            int s2 = __shfl_sync(0xFFFFFFFFu, e2.x, l + 2);
            int s3 = __shfl_sync(0xFFFFFFFFu, e2.x, l + 3);
            float w0 = __int_as_float(__shfl_sync(0xFFFFFFFFu, e2.y, l));
            float w1 = __int_as_float(__shfl_sync(0xFFFFFFFFu, e2.y, l + 1));
            float w2 = __int_as_float(__shfl_sync(0xFFFFFFFFu, e2.y, l + 2));
            float w3 = __int_as_float(__shfl_sync(0xFFFFFFFFu, e2.y, l + 3));
            const __half2* r0 = h2 + (size_t)s0 * H2;
            const __half2* r1 = h2 + (size_t)s1 * H2;
            const __half2* r2 = h2 + (size_t)s2 * H2;
            const __half2* r3 = h2 + (size_t)s3 * H2;
            // issue all 12(+tail) loads before consuming
            __half2 p0 = r0[lane],      p1 = r1[lane],      p2 = r2[lane],      p3 = r3[lane];
            __half2 q0 = r0[32 + lane], q1 = r1[32 + lane], q2 = r2[32 + lane], q3 = r3[32 + lane];
            __half2 t0, t1, t2, t3;
            if (tl) { t0 = r0[64 + lane]; t1 = r1[64 + lane]; t2 = r2[64 + lane]; t3 = r3[64 + lane]; }
            float2 f;
            f = __half22float2(p0); a0.x = fmaf(w0, f.x, a0.x); a0.y = fmaf(w0, f.y, a0.y);
            f = __half22float2(p1); a0.x = fmaf(w1, f.x, a0.x); a0.y = fmaf(w1, f.y, a0.y);
            f = __half22float2(p2); a0.x = fmaf(w2, f.x, a0.x); a0.y = fmaf(w2, f.y, a0.y);
            f = __half22float2(p3); a0.x = fmaf(w3, f.x, a0.x); a0.y = fmaf(w3, f.y, a0.y);
            f = __half22float2(q0); a1.x = fmaf(w0, f.x, a1.x); a1.y = fmaf(w0, f.y, a1.y);
            f = __half22float2(q1); a1.x = fmaf(w1, f.x, a1.x); a1.y = fmaf(w1, f.y, a1.y);
            f = __half22float2(q2); a1.x = fmaf(w2, f.x, a1.x); a1.y = fmaf(w2, f.y, a1.y);
            f = __half22float2(q3); a1.x = fmaf(w3, f.x, a1.x); a1.y = fmaf(w3, f.y, a1.y);
            if (tl) {
                f = __half22float2(t0); a2.x = fmaf(w0, f.x, a2.x); a2.y = fmaf(w0, f.y, a2.y);
                f = __half22float2(t1); a2.x = fmaf(w1, f.x, a2.x); a2.y = fmaf(w1, f.y, a2.y);
                f = __half22float2(t2); a2.x = fmaf(w2, f.x, a2.x); a2.y = fmaf(w2, f.y, a2.y);
                f = __half22float2(t3); a2.x = fmaf(w3, f.x, a2.x); a2.y = fmaf(w3, f.y, a2.y);
            }
        }
        for (; l < cnt; l++) {
            int src = __shfl_sync(0xFFFFFFFFu, e2.x, l);
            float w = __int_as_float(__shfl_sync(0xFFFFFFFFu, e2.y, l));
            const __half2* hr = h2 + (size_t)src * H2;
            float2 p = __half22float2(hr[lane]);
            float2 q = __half22float2(hr[32 + lane]);
            a0.x = fmaf(w, p.x, a0.x); a0.y = fmaf(w, p.y, a0.y);
            a1.x = fmaf(w, q.x, a1.x); a1.y = fmaf(w, q.y, a1.y);
            if (tl) {
                float2 r = __half22float2(hr[64 + lane]);
                a2.x = fmaf(w, r.x, a2.x); a2.y = fmaf(w, r.y, a2.y);
            }
        }
    }

    // epilogue: bias + ReLU + precomputed BN affine -> fp16 store
    const float* sc = g_sc[layer];
    const float* sh = g_sh[layer];
    __half2* t2 = (__half2*)g_t + (size_t)node * H2;
    {
        int d = 2 * lane;
        float vx = fmaxf(a0.x + b[d], 0.f)     * sc[d]     + sh[d];
        float vy = fmaxf(a0.y + b[d + 1], 0.f) * sc[d + 1] + sh[d + 1];
        t2[lane] = __floats2half2_rn(vx, vy);
    }
    {
        int d = 64 + 2 * lane;
        float vx = fmaxf(a1.x + b[d], 0.f)     * sc[d]     + sh[d];
        float vy = fmaxf(a1.y + b[d + 1], 0.f) * sc[d + 1] + sh[d + 1];
        t2[32 + lane] = __floats2half2_rn(vx, vy);
    }
    if (tl) {
        int d = 128 + 2 * lane;                 // 128,130,132 (133..135 pad: sc/sh=0)
        float vx = fmaxf(a2.x + b[d], 0.f) * sc[d] + sh[d];
        float vy = 0.f;
        if (d + 1 < DIM) vy = fmaxf(a2.y + b[d + 1], 0.f) * sc[d + 1] + sh[d + 1];
        t2[64 + lane] = __floats2half2_rn(vx, vy);
    }
}

// ---------------- pooling: one warp per graph, no atomics ----------------
__global__ __launch_bounds__(256) void pool_kernel(float* __restrict__ out) {
    int g = (blockIdx.x * blockDim.x + threadIdx.x) >> 5;
    int lane = threadIdx.x & 31;
    if (g >= N_GRAPHS) return;
    int s = g_goff[g], e = g_goff[g + 1];
    const __half2* __restrict__ t2 = (const __half2*)g_t;
    float2 a0 = make_float2(0.f, 0.f);
    float2 a1 = make_float2(0.f, 0.f);
    float2 a2 = make_float2(0.f, 0.f);
    for (int n = s; n < e; n++) {
        const __half2* r = t2 + (size_t)n * H2;
        float2 p = __half22float2(r[lane]);
        float2 q = __half22float2(r[32 + lane]);
        a0.x += p.x; a0.y += p.y;
        a1.x += q.x; a1.y += q.y;
        if (lane < 3) {
            float2 rr = __half22float2(r[64 + lane]);
            a2.x += rr.x; a2.y += rr.y;
        }
    }
    float inv = 1.f / fmaxf((float)(e - s), 1.f);
    int d0 = 2 * lane;
    out[g * DIM + d0]     = a0.x * inv;
    out[g * DIM + d0 + 1] = a0.y * inv;
    out[g * DIM + 64 + d0]     = a1.x * inv;
    out[g * DIM + 64 + d0 + 1] = a1.y * inv;
    if (lane < 3) {
        int d = 128 + 2 * lane;
        out[g * DIM + d] = a2.x * inv;
        if (d + 1 < DIM) out[g * DIM + d + 1] = a2.y * inv;
    }
}

// ---------------- launch ----------------
extern "C" void kernel_launch(void* const* d_in, const int* in_sizes, int n_in,
                              void* d_out, int out_size) {
    const float* x     = (const float*)d_in[0];
    const int*   ei    = (const int*)d_in[1];   // [2, E] int32
    const int*   batch = (const int*)d_in[2];   // [N] int32
    const float* W1 = (const float*)d_in[3];
    const float* b1 = (const float*)d_in[4];
    const float* W2 = (const float*)d_in[5];
    const float* b2 = (const float*)d_in[6];
    const float* g1 = (const float*)d_in[7];
    const float* be1 = (const float*)d_in[8];
    const float* rm1 = (const float*)d_in[9];
    const float* rv1 = (const float*)d_in[10];
    const float* g2 = (const float*)d_in[11];
    const float* be2 = (const float*)d_in[12];
    const float* rm2 = (const float*)d_in[13];
    const float* rv2 = (const float*)d_in[14];
    float* out = (float*)d_out;

    const int* row = ei;            // first E entries
    const int* col = ei + N_EDGES;  // second E entries

    const int SMEM_W = WSTRIDE * WSTRIDE * 4;   // 73984 bytes
    cudaFuncSetAttribute(gemm_tc_kernel,
                         cudaFuncAttributeMaxDynamicSharedMemorySize, SMEM_W);

    // 1. CSR build (+ per-graph ranges + BN affine precompute)
    prep_kernel<<<NB, 256>>>(batch, g1, be1, rm1, rv1, g2, be2, rm2, rv2);
    hist_kernel<<<2048, 256>>>(col);
    reduce_kernel<<<NB, 256>>>();
    scan_apply_kernel<<<NB, 256>>>();
    scatter_kernel<<<2048, 256>>>(row, col);

    // 2. layer 1: tf32 GEMM -> aggregate (+bias, ReLU, BN fused)
    gemm_tc_kernel<<<(N_NODES + 63) / 64, 128, SMEM_W>>>(x, W1, 0);
    agg_kernel<<<(N_NODES * 32 + 255) / 256, 256>>>(b1, 0);

    // 3. layer 2 (A comes from g_t, fp16)
    gemm_tc_kernel<<<(N_NODES + 63) / 64, 128, SMEM_W>>>(x, W2, 1);
    agg_kernel<<<(N_NODES * 32 + 255) / 256, 256>>>(b2, 1);

    // 4. global mean pool (sorted batch -> contiguous ranges, no atomics)
    pool_kernel<<<(N_GRAPHS * 32 + 255) / 256, 256>>>(out);
}